// round 2
// baseline (speedup 1.0000x reference)
#include <cuda_runtime.h>

// Problem constants
#define NB 4
#define SLEN 32768
#define C1 128
#define C2C 256
#define C3 512
#define L1O 16384
#define L2O 8192
#define L3O 4096
#define VOCAB 2048
#define KCB 4
#define NCODES (KCB * VOCAB)   // 8192
#define MTOT (NB * L3O)        // 16384
#define NTILE 128
#define NT (NCODES / NTILE)    // 64 n-tiles total, 16 per codebook

// Scratch (device globals: alloc-free)
__device__ float g_f1[NB * C1 * L1O];     // 33.5 MB
__device__ float g_f2[NB * C2C * L2O];    // 33.5 MB
__device__ float g_f3[NB * C3 * L3O];     // 33.5 MB
__device__ float g_c2[NCODES];
__device__ float g_pmin[MTOT * NT];       // 4 MB
__device__ int   g_pidx[MTOT * NT];       // 4 MB

// ---------------------------------------------------------------------------
// conv1: [B,1,32768] -> relu -> [B,128,16384], k=7, stride=2, pad=3
// ---------------------------------------------------------------------------
__global__ void conv1_kernel(const float* __restrict__ x,
                             const float* __restrict__ w,
                             const float* __restrict__ bias,
                             float* __restrict__ out) {
    int l  = blockIdx.x * 256 + threadIdx.x;
    int co = blockIdx.y;
    int b  = blockIdx.z;
    if (l >= L1O) return;
    const float* xb = x + b * SLEN;
    float acc = bias[co];
#pragma unroll
    for (int t = 0; t < 7; ++t) {
        int g = 2 * l + t - 3;
        float xv = (g >= 0 && g < SLEN) ? xb[g] : 0.0f;
        acc = fmaf(w[co * 7 + t], xv, acc);
    }
    out[(b * C1 + co) * L1O + l] = fmaxf(acc, 0.0f);
}

// ---------------------------------------------------------------------------
// Tiled conv: in [B,CI,L_in] -> out [B,CO,L_out], k=7, stride=2, pad=3
// Tile: 64 output positions x 128 output channels, ci chunks of 8.
// Block 256 = 16(tx: l) x 16(ty: co). Per-thread 4l x 8co register tile.
// ---------------------------------------------------------------------------
template <int CI>
__global__ void conv_tiled(const float* __restrict__ in,
                           const float* __restrict__ w,
                           const float* __restrict__ bias,
                           float* __restrict__ out,
                           int L_in, int L_out, int CO, int do_relu) {
    constexpr int TL = 64, TCO = 128, CC = 8;
    __shared__ float sIn[CC][2 * TL + 16];      // 8 x 144
    __shared__ float sW[CC][7][TCO];            // 8 x 7 x 128

    const int tx = threadIdx.x & 15;
    const int ty = threadIdx.x >> 4;
    const int l0  = blockIdx.x * TL;
    const int co0 = blockIdx.y * TCO;
    const int b   = blockIdx.z;

    float acc[4][8];
#pragma unroll
    for (int i = 0; i < 4; ++i)
#pragma unroll
        for (int j = 0; j < 8; ++j) acc[i][j] = 0.0f;

    const int in_base = 2 * l0 - 3;   // global input pos of sIn[ci][0]

    for (int c0 = 0; c0 < CI; c0 += CC) {
        // load input slab: CC x 134 (span needed for 64 outputs)
        for (int i = threadIdx.x; i < CC * 144; i += 256) {
            int ci = i / 144, j = i % 144;
            float v = 0.0f;
            int g = in_base + j;
            if (j < 134 && g >= 0 && g < L_in)
                v = in[((size_t)b * CI + (c0 + ci)) * L_in + g];
            sIn[ci][j] = v;
        }
        // load weights: w layout [CO][CI][7]
        for (int i = threadIdx.x; i < CC * 7 * TCO; i += 256) {
            int ci = i / (7 * TCO);
            int r  = i % (7 * TCO);
            int t  = r / TCO;
            int co = r % TCO;
            sW[ci][t][co] = w[((size_t)(co0 + co) * CI + (c0 + ci)) * 7 + t];
        }
        __syncthreads();

#pragma unroll
        for (int ci = 0; ci < CC; ++ci) {
            float xr[13];
#pragma unroll
            for (int j = 0; j < 13; ++j) xr[j] = sIn[ci][8 * tx + j];
#pragma unroll
            for (int t = 0; t < 7; ++t) {
                float4 w0 = *(const float4*)&sW[ci][t][ty * 8];
                float4 w1 = *(const float4*)&sW[ci][t][ty * 8 + 4];
                float wv[8] = {w0.x, w0.y, w0.z, w0.w, w1.x, w1.y, w1.z, w1.w};
#pragma unroll
                for (int il = 0; il < 4; ++il) {
                    float xv = xr[2 * il + t];
#pragma unroll
                    for (int ic = 0; ic < 8; ++ic)
                        acc[il][ic] = fmaf(xv, wv[ic], acc[il][ic]);
                }
            }
        }
        __syncthreads();
    }

#pragma unroll
    for (int il = 0; il < 4; ++il) {
        int l = l0 + tx * 4 + il;
#pragma unroll
        for (int ic = 0; ic < 8; ++ic) {
            int co = co0 + ty * 8 + ic;
            float v = acc[il][ic] + bias[co];
            if (do_relu) v = fmaxf(v, 0.0f);
            out[((size_t)b * CO + co) * L_out + l] = v;
        }
    }
}

// ---------------------------------------------------------------------------
// c2[n] = sum_h codebook[n][h]^2, n in [0, 8192). One warp per row.
// ---------------------------------------------------------------------------
__global__ void c2_kernel(const float* __restrict__ cb, float* __restrict__ c2) {
    int warp = blockIdx.x * 8 + (threadIdx.x >> 5);
    int lane = threadIdx.x & 31;
    if (warp >= NCODES) return;
    const float* row = cb + (size_t)warp * 512;
    float s = 0.0f;
#pragma unroll
    for (int h = lane; h < 512; h += 32) { float v = row[h]; s = fmaf(v, v, s); }
#pragma unroll
    for (int o = 16; o > 0; o >>= 1) s += __shfl_down_sync(0xffffffffu, s, o);
    if (lane == 0) c2[warp] = s;
}

// ---------------------------------------------------------------------------
// Fused VQ GEMM + per-tile argmin.
// A: feats^T stored as f3 [B][512][4096]  (M = b*4096+l, K = 512)
// Bmat: codebook [8192][512]              (N = k*2048+v)
// score = c2[n] - 2 * dot(A_m, B_n); per 64x128 tile reduce argmin per row.
// ---------------------------------------------------------------------------
__global__ void vq_gemm(const float* __restrict__ f3,
                        const float* __restrict__ cb,
                        const float* __restrict__ c2,
                        float* __restrict__ pmin, int* __restrict__ pidx) {
    constexpr int TM = 64, TN = 128, KC = 8;
    __shared__ float sA[KC][TM + 4];
    __shared__ float sB[KC][TN + 4];
    __shared__ float rmin[TM][17];
    __shared__ int   ridx[TM][17];

    const int tx = threadIdx.x & 15;   // m group (4 rows each)
    const int ty = threadIdx.x >> 4;   // n group (8 cols each)
    const int m0 = blockIdx.x * TM;
    const int n0 = blockIdx.y * TN;
    const int b  = m0 / L3O;           // TM divides 4096 -> one b per block
    const int l0 = m0 % L3O;

    float acc[4][8];
#pragma unroll
    for (int i = 0; i < 4; ++i)
#pragma unroll
        for (int j = 0; j < 8; ++j) acc[i][j] = 0.0f;

    for (int k0 = 0; k0 < 512; k0 += KC) {
        for (int i = threadIdx.x; i < KC * TM; i += 256) {
            int kk = i / TM, j = i % TM;
            sA[kk][j] = f3[((size_t)b * 512 + k0 + kk) * L3O + l0 + j];
        }
        for (int i = threadIdx.x; i < KC * TN; i += 256) {
            int kk = i % KC, n = i / KC;
            sB[kk][n] = cb[(size_t)(n0 + n) * 512 + k0 + kk];
        }
        __syncthreads();
#pragma unroll
        for (int kk = 0; kk < KC; ++kk) {
            float4 av  = *(const float4*)&sA[kk][tx * 4];
            float4 bv0 = *(const float4*)&sB[kk][ty * 8];
            float4 bv1 = *(const float4*)&sB[kk][ty * 8 + 4];
            float a[4] = {av.x, av.y, av.z, av.w};
            float bb[8] = {bv0.x, bv0.y, bv0.z, bv0.w, bv1.x, bv1.y, bv1.z, bv1.w};
#pragma unroll
            for (int il = 0; il < 4; ++il)
#pragma unroll
                for (int ic = 0; ic < 8; ++ic)
                    acc[il][ic] = fmaf(a[il], bb[ic], acc[il][ic]);
        }
        __syncthreads();
    }

    // epilogue: argmin of c2[n] - 2*cross within this thread's 8 columns
#pragma unroll
    for (int il = 0; il < 4; ++il) {
        float bestv = 3.4e38f;
        int   besti = 0;
#pragma unroll
        for (int ic = 0; ic < 8; ++ic) {
            int n = n0 + ty * 8 + ic;
            float s = c2[n] - 2.0f * acc[il][ic];
            if (s < bestv) { bestv = s; besti = n; }   // strict < : lowest idx on tie
        }
        rmin[tx * 4 + il][ty] = bestv;
        ridx[tx * 4 + il][ty] = besti;
    }
    __syncthreads();

    if (threadIdx.x < TM) {
        int m = threadIdx.x;
        float bv = rmin[m][0];
        int   bi = ridx[m][0];
#pragma unroll
        for (int j = 1; j < 16; ++j) {
            float v = rmin[m][j];
            if (v < bv) { bv = v; bi = ridx[m][j]; }   // ascending n -> first-occurrence
        }
        pmin[(size_t)(m0 + m) * NT + blockIdx.y] = bv;
        pidx[(size_t)(m0 + m) * NT + blockIdx.y] = bi;
    }
}

// ---------------------------------------------------------------------------
// Finalize: per (b,l) reduce 16 partials per codebook -> tokens (as float),
// then emb = mean of the 4 embedding rows.
// out layout: [tokens B*K*L floats][emb B*L*H floats]
// ---------------------------------------------------------------------------
__global__ void finalize_kernel(const float* __restrict__ pmin,
                                const int* __restrict__ pidx,
                                const float* __restrict__ emb_table,
                                float* __restrict__ out) {
    __shared__ int tok[KCB];
    const int m = blockIdx.x;            // 0..16383
    const int b = m / L3O, l = m % L3O;
    const int tid = threadIdx.x;         // 128 threads

    if (tid < KCB) {
        int cbk = tid;
        float bv = 3.4e38f;
        int bi = 0;
        for (int j = 0; j < 16; ++j) {
            int idx = m * NT + cbk * 16 + j;
            float v = pmin[idx];
            if (v < bv) { bv = v; bi = pidx[idx]; }  // tiles ordered by n -> first-occ
        }
        int t = bi & (VOCAB - 1);
        tok[cbk] = t;
        out[((size_t)b * KCB + cbk) * L3O + l] = (float)t;
    }
    __syncthreads();

    float* out_emb = out + (size_t)NB * KCB * L3O;
    int t0 = tok[0], t1 = tok[1], t2 = tok[2], t3 = tok[3];
    for (int h = tid; h < 512; h += 128) {
        float s = emb_table[(size_t)t0 * 512 + h] + emb_table[(size_t)t1 * 512 + h]
                + emb_table[(size_t)t2 * 512 + h] + emb_table[(size_t)t3 * 512 + h];
        out_emb[((size_t)b * L3O + l) * 512 + h] = 0.25f * s;
    }
}

// ---------------------------------------------------------------------------
extern "C" void kernel_launch(void* const* d_in, const int* in_sizes, int n_in,
                              void* d_out, int out_size) {
    const float* audio = (const float*)d_in[0];
    const float* w1    = (const float*)d_in[1];
    const float* b1    = (const float*)d_in[2];
    const float* w2    = (const float*)d_in[3];
    const float* b2    = (const float*)d_in[4];
    const float* w3    = (const float*)d_in[5];
    const float* b3    = (const float*)d_in[6];
    const float* cb    = (const float*)d_in[7];
    const float* emb   = (const float*)d_in[8];
    float* out = (float*)d_out;

    float *f1, *f2, *f3, *c2p, *pmin;
    int* pidx;
    cudaGetSymbolAddress((void**)&f1, g_f1);
    cudaGetSymbolAddress((void**)&f2, g_f2);
    cudaGetSymbolAddress((void**)&f3, g_f3);
    cudaGetSymbolAddress((void**)&c2p, g_c2);
    cudaGetSymbolAddress((void**)&pmin, g_pmin);
    cudaGetSymbolAddress((void**)&pidx, g_pidx);

    // conv1
    conv1_kernel<<<dim3(L1O / 256, C1, NB), 256>>>(audio, w1, b1, f1);
    // conv2: 128 -> 256
    conv_tiled<C1><<<dim3(L2O / 64, C2C / 128, NB), 256>>>(f1, w2, b2, f2, L1O, L2O, C2C, 1);
    // conv3: 256 -> 512 (no relu)
    conv_tiled<C2C><<<dim3(L3O / 64, C3 / 128, NB), 256>>>(f2, w3, b3, f3, L2O, L3O, C3, 0);
    // codebook norms
    c2_kernel<<<NCODES / 8, 256>>>(cb, c2p);
    // VQ GEMM + tile argmin
    vq_gemm<<<dim3(MTOT / 64, NCODES / NTILE), 256>>>(f3, cb, c2p, pmin, pidx);
    // tokens + embedding mean
    finalize_kernel<<<MTOT, 128>>>(pmin, pidx, emb, out);
}

// round 3
// speedup vs baseline: 2.4185x; 2.4185x over previous
#include <cuda_runtime.h>
#include <cstdint>

// Problem constants
#define NB 4
#define SLEN 32768
#define C1 128
#define C2C 256
#define C3 512
#define L1O 16384
#define L2O 8192
#define L3O 4096
#define VOCAB 2048
#define KCB 4
#define NCODES (KCB * VOCAB)   // 8192
#define MTOT (NB * L3O)        // 16384
#define NT 64                  // 8192 / 128 n-tiles, 16 per codebook

// Scratch (device globals: alloc-free)
__device__ float g_f1[NB * C1 * L1O];               // 33.5 MB
__device__ float g_f2[NB * C2C * L2O];              // 33.5 MB
__device__ float g_f3[NB * C3 * L3O];               // 33.5 MB
__device__ float g_cbT[512 * NCODES];               // 16 MB  (codebook^T: [k][n])
__device__ float g_c2[NCODES];
__device__ unsigned long long g_pkey[MTOT * NT];    // 8 MB

// ---------------------------------------------------------------------------
// packed f32x2 helpers (FFMA2 path — only reachable via PTX)
// ---------------------------------------------------------------------------
__device__ __forceinline__ unsigned long long pack2(float lo, float hi) {
    unsigned long long r;
    asm("mov.b64 %0, {%1, %2};" : "=l"(r) : "f"(lo), "f"(hi));
    return r;
}
__device__ __forceinline__ void unpack2(unsigned long long v, float& lo, float& hi) {
    asm("mov.b64 {%0, %1}, %2;" : "=f"(lo), "=f"(hi) : "l"(v));
}
__device__ __forceinline__ void fma2(unsigned long long& d,
                                     unsigned long long a, unsigned long long b) {
    asm("fma.rn.f32x2 %0, %1, %2, %0;" : "+l"(d) : "l"(a), "l"(b));
}

// cp.async helpers
__device__ __forceinline__ void cp16(uint32_t dst, const void* src) {
    asm volatile("cp.async.cg.shared.global [%0], [%1], 16;" :: "r"(dst), "l"(src));
}
__device__ __forceinline__ void cp_commit() {
    asm volatile("cp.async.commit_group;");
}
__device__ __forceinline__ void cp_wait1() {
    asm volatile("cp.async.wait_group 1;");
}

// ordered key: (monotonic float bits << 32) | index  -> u64 min == argmin w/ lowest-idx tie
__device__ __forceinline__ unsigned long long dist_key(float v, int n) {
    unsigned int fb = __float_as_uint(v);
    fb = (fb & 0x80000000u) ? ~fb : (fb | 0x80000000u);
    return ((unsigned long long)fb << 32) | (unsigned int)n;
}

// ---------------------------------------------------------------------------
// conv1: [B,1,32768] -> relu -> [B,128,16384], k=7, stride=2, pad=3
// ---------------------------------------------------------------------------
__global__ void conv1_kernel(const float* __restrict__ x,
                             const float* __restrict__ w,
                             const float* __restrict__ bias,
                             float* __restrict__ out) {
    int l  = blockIdx.x * 256 + threadIdx.x;
    int co = blockIdx.y;
    int b  = blockIdx.z;
    if (l >= L1O) return;
    const float* xb = x + b * SLEN;
    float acc = bias[co];
#pragma unroll
    for (int t = 0; t < 7; ++t) {
        int g = 2 * l + t - 3;
        float xv = (g >= 0 && g < SLEN) ? xb[g] : 0.0f;
        acc = fmaf(w[co * 7 + t], xv, acc);
    }
    out[(b * C1 + co) * L1O + l] = fmaxf(acc, 0.0f);
}

// ---------------------------------------------------------------------------
// Tiled conv (f32x2): in [B,CI,L_in] -> out [B,CO,L_out], k=7, stride=2, pad=3
// Tile 128 L x 128 CO; 256 threads; per-thread 8L x 8CO (packed pairs on CO).
// Input slab stored with +4-floats-per-16 pad to avoid 64B-stride conflicts.
// ---------------------------------------------------------------------------
#define CSPAN 262                 // 2*128 + 6 input positions needed
#define CMAP(j) ((j) + (((j) >> 4) << 2))
#define CWID 336                  // mapped width (max mapped 325), padded

template <int CI>
__global__ __launch_bounds__(256) void conv_tiled(
        const float* __restrict__ in, const float* __restrict__ w,
        const float* __restrict__ bias, float* __restrict__ out,
        int L_in, int L_out, int CO, int do_relu) {
    constexpr int TL = 128, TCO = 128, CC = 8;
    __shared__ __align__(16) float sIn[CC][CWID];
    __shared__ __align__(16) float sW[CC][7][TCO];

    const int tid = threadIdx.x;
    const int tx = tid & 15;          // l group  (8 outputs each)
    const int ty = tid >> 4;          // co group (8 outputs each, 4 packed pairs)
    const int l0  = blockIdx.x * TL;
    const int co0 = blockIdx.y * TCO;
    const int b   = blockIdx.z;
    const int in_base = 2 * l0 - 3;

    unsigned long long acc[8][4];
#pragma unroll
    for (int i = 0; i < 8; ++i)
#pragma unroll
        for (int j = 0; j < 4; ++j) acc[i][j] = 0ull;   // +0.0f pair

    for (int c0 = 0; c0 < CI; c0 += CC) {
        // input slab
        for (int i = tid; i < CC * 264; i += 256) {
            int ci = i / 264, j = i % 264;
            if (j < CSPAN) {
                float v = 0.0f;
                int g = in_base + j;
                if (g >= 0 && g < L_in)
                    v = in[((size_t)b * CI + (c0 + ci)) * L_in + g];
                sIn[ci][CMAP(j)] = v;
            }
        }
        // weights: w layout [CO][CI][7]
        for (int i = tid; i < CC * 7 * TCO; i += 256) {
            int ci = i / (7 * TCO);
            int r  = i % (7 * TCO);
            int t  = r / TCO;
            int co = r % TCO;
            sW[ci][t][co] = w[((size_t)(co0 + co) * CI + (c0 + ci)) * 7 + t];
        }
        __syncthreads();

#pragma unroll
        for (int ci = 0; ci < CC; ++ci) {
            // load 21 input values (mapped base 20*tx), pack as dup pairs
            float xr[24];
            *(float4*)&xr[0]  = *(const float4*)&sIn[ci][20 * tx];
            *(float4*)&xr[4]  = *(const float4*)&sIn[ci][20 * tx + 4];
            *(float4*)&xr[8]  = *(const float4*)&sIn[ci][20 * tx + 8];
            *(float4*)&xr[12] = *(const float4*)&sIn[ci][20 * tx + 12];
            *(float4*)&xr[16] = *(const float4*)&sIn[ci][20 * tx + 20]; // logical 16..19
            xr[20] = sIn[ci][20 * tx + 24];                             // logical 20
            unsigned long long xd[21];
#pragma unroll
            for (int j = 0; j < 21; ++j) xd[j] = pack2(xr[j], xr[j]);

#pragma unroll
            for (int t = 0; t < 7; ++t) {
                ulonglong2 w0 = *(const ulonglong2*)&sW[ci][t][ty * 8];
                ulonglong2 w1 = *(const ulonglong2*)&sW[ci][t][ty * 8 + 4];
                unsigned long long wv[4] = {w0.x, w0.y, w1.x, w1.y};
#pragma unroll
                for (int il = 0; il < 8; ++il)
#pragma unroll
                    for (int jc = 0; jc < 4; ++jc)
                        fma2(acc[il][jc], xd[2 * il + t], wv[jc]);
            }
        }
        __syncthreads();
    }

#pragma unroll
    for (int il = 0; il < 8; ++il) {
        int l = l0 + tx * 8 + il;
#pragma unroll
        for (int jc = 0; jc < 4; ++jc) {
            float v0, v1;
            unpack2(acc[il][jc], v0, v1);
            int co = co0 + ty * 8 + jc * 2;
            v0 += bias[co];
            v1 += bias[co + 1];
            if (do_relu) { v0 = fmaxf(v0, 0.0f); v1 = fmaxf(v1, 0.0f); }
            out[((size_t)b * CO + co)     * L_out + l] = v0;
            out[((size_t)b * CO + co + 1) * L_out + l] = v1;
        }
    }
}

// ---------------------------------------------------------------------------
// codebook transpose: cb [8192][512] -> cbT [512][8192]
// ---------------------------------------------------------------------------
__global__ void transpose_cb(const float* __restrict__ cb, float* __restrict__ cbT) {
    __shared__ float t[32][33];
    int k = blockIdx.x * 32 + threadIdx.x;
    int n0 = blockIdx.y * 32;
#pragma unroll
    for (int i = threadIdx.y; i < 32; i += 8)
        t[i][threadIdx.x] = cb[(size_t)(n0 + i) * 512 + k];
    __syncthreads();
    int nt = n0 + threadIdx.x;
    int k0 = blockIdx.x * 32;
#pragma unroll
    for (int i = threadIdx.y; i < 32; i += 8)
        cbT[(size_t)(k0 + i) * NCODES + nt] = t[threadIdx.x][i];
}

// ---------------------------------------------------------------------------
// c2[n] = sum_h codebook[n][h]^2. One warp per row.
// ---------------------------------------------------------------------------
__global__ void c2_kernel(const float* __restrict__ cb, float* __restrict__ c2) {
    int warp = blockIdx.x * 8 + (threadIdx.x >> 5);
    int lane = threadIdx.x & 31;
    if (warp >= NCODES) return;
    const float* row = cb + (size_t)warp * 512;
    float s = 0.0f;
#pragma unroll
    for (int h = lane; h < 512; h += 32) { float v = row[h]; s = fmaf(v, v, s); }
#pragma unroll
    for (int o = 16; o > 0; o >>= 1) s += __shfl_down_sync(0xffffffffu, s, o);
    if (lane == 0) c2[warp] = s;
}

// ---------------------------------------------------------------------------
// Fused VQ GEMM + per-tile argmin (f32x2, cp.async double-buffered).
// A: f3 [B][512][4096] (k-major, m contiguous);  B: cbT [512][8192].
// Block tile 128m x 128n, KC=16, 256 threads, 8x8 per thread.
// ---------------------------------------------------------------------------
#define VTM 128
#define VTN 128
#define VKC 16

__global__ __launch_bounds__(256) void vq_gemm(
        const float* __restrict__ f3, const float* __restrict__ cbT,
        const float* __restrict__ c2, unsigned long long* __restrict__ pkey) {
    // 2 buffers x (A 16x128 + B 16x128) floats = 32 KB; reused for reduction
    __shared__ __align__(16) char smem_raw[2 * VKC * (VTM + VTN) * 4];
    float* sA = (float*)smem_raw;                               // [2][VKC][VTM]
    float* sB = (float*)(smem_raw + 2 * VKC * VTM * 4);         // [2][VKC][VTN]
    const uint32_t sA_u = (uint32_t)__cvta_generic_to_shared(sA);
    const uint32_t sB_u = (uint32_t)__cvta_generic_to_shared(sB);

    const int tid = threadIdx.x;
    const int tx = tid & 15;          // n group (8 cols)
    const int ty = tid >> 4;          // m group (8 rows)
    const int m0 = blockIdx.x * VTM;
    const int n0 = blockIdx.y * VTN;
    const int b  = m0 >> 12;
    const int l0 = m0 & 4095;
    const float* Abase = f3 + (size_t)b * 512 * 4096 + l0;
    const float* Bbase = cbT + n0;

    unsigned long long acc[8][4];
#pragma unroll
    for (int i = 0; i < 8; ++i)
#pragma unroll
        for (int j = 0; j < 4; ++j) acc[i][j] = 0ull;

    // chunk loader: 256 threads x 2 x (A seg + B seg)
    auto load_chunk = [&](int c, int buf) {
        int k0 = c * VKC;
#pragma unroll
        for (int r = 0; r < 2; ++r) {
            int i = tid + r * 256;            // 0..511
            int kk = i >> 5;
            int off = (i & 31) * 4;
            cp16(sA_u + (((buf * VKC + kk) * VTM + off) << 2),
                 Abase + (size_t)(k0 + kk) * 4096 + off);
            cp16(sB_u + (((buf * VKC + kk) * VTN + off) << 2),
                 Bbase + (size_t)(k0 + kk) * NCODES + off);
        }
    };

    load_chunk(0, 0);
    cp_commit();

    const int NCHUNK = 512 / VKC;     // 32
    for (int c = 0; c < NCHUNK; ++c) {
        if (c + 1 < NCHUNK) load_chunk(c + 1, (c + 1) & 1);
        cp_commit();
        cp_wait1();
        __syncthreads();

        const float* Ac = sA + (c & 1) * VKC * VTM;
        const float* Bc = sB + (c & 1) * VKC * VTN;
#pragma unroll
        for (int kk = 0; kk < VKC; ++kk) {
            float4 a0 = *(const float4*)(Ac + kk * VTM + ty * 8);
            float4 a1 = *(const float4*)(Ac + kk * VTM + ty * 8 + 4);
            ulonglong2 b0 = *(const ulonglong2*)(Bc + kk * VTN + tx * 8);
            ulonglong2 b1 = *(const ulonglong2*)(Bc + kk * VTN + tx * 8 + 4);
            unsigned long long bb[4] = {b0.x, b0.y, b1.x, b1.y};
            float av[8] = {a0.x, a0.y, a0.z, a0.w, a1.x, a1.y, a1.z, a1.w};
#pragma unroll
            for (int im = 0; im < 8; ++im) {
                unsigned long long ad = pack2(av[im], av[im]);
#pragma unroll
                for (int jn = 0; jn < 4; ++jn) fma2(acc[im][jn], ad, bb[jn]);
            }
        }
        __syncthreads();
    }

    // epilogue: per-row argmin of c2[n] - 2*cross over this thread's 8 cols
    unsigned long long* sRed = (unsigned long long*)smem_raw;   // [128][16] = 16 KB
#pragma unroll
    for (int im = 0; im < 8; ++im) {
        int m = ty * 8 + im;
        unsigned long long best = ~0ull;
#pragma unroll
        for (int jn = 0; jn < 4; ++jn) {
            float lo, hi;
            unpack2(acc[im][jn], lo, hi);
            int n = n0 + tx * 8 + jn * 2;
            unsigned long long k0 = dist_key(c2[n]     - 2.0f * lo, n);
            unsigned long long k1 = dist_key(c2[n + 1] - 2.0f * hi, n + 1);
            if (k0 < best) best = k0;
            if (k1 < best) best = k1;
        }
        sRed[m * 16 + tx] = best;
    }
    __syncthreads();

    if (tid < VTM) {
        unsigned long long best = sRed[tid * 16];
#pragma unroll
        for (int j = 1; j < 16; ++j) {
            unsigned long long v = sRed[tid * 16 + j];
            if (v < best) best = v;
        }
        pkey[(size_t)(m0 + tid) * NT + blockIdx.y] = best;
    }
}

// ---------------------------------------------------------------------------
// Finalize: per (b,l) reduce 16 key-partials per codebook -> tokens (float),
// then emb = mean of the 4 embedding rows.
// ---------------------------------------------------------------------------
__global__ void finalize_kernel(const unsigned long long* __restrict__ pkey,
                                const float* __restrict__ emb_table,
                                float* __restrict__ out) {
    __shared__ int tok[KCB];
    const int m = blockIdx.x;            // 0..16383
    const int b = m >> 12, l = m & 4095;
    const int tid = threadIdx.x;         // 128 threads

    if (tid < KCB) {
        unsigned long long best = ~0ull;
#pragma unroll
        for (int j = 0; j < 16; ++j) {
            unsigned long long v = pkey[(size_t)m * NT + tid * 16 + j];
            if (v < best) best = v;
        }
        int t = ((int)(best & 0xffffffffu)) & (VOCAB - 1);
        tok[tid] = t;
        out[((size_t)b * KCB + tid) * L3O + l] = (float)t;
    }
    __syncthreads();

    float* out_emb = out + (size_t)NB * KCB * L3O;
    int t0 = tok[0], t1 = tok[1], t2 = tok[2], t3 = tok[3];
    for (int h = tid; h < 512; h += 128) {
        float s = emb_table[(size_t)t0 * 512 + h] + emb_table[(size_t)t1 * 512 + h]
                + emb_table[(size_t)t2 * 512 + h] + emb_table[(size_t)t3 * 512 + h];
        out_emb[((size_t)b * L3O + l) * 512 + h] = 0.25f * s;
    }
}

// ---------------------------------------------------------------------------
extern "C" void kernel_launch(void* const* d_in, const int* in_sizes, int n_in,
                              void* d_out, int out_size) {
    const float* audio = (const float*)d_in[0];
    const float* w1    = (const float*)d_in[1];
    const float* b1    = (const float*)d_in[2];
    const float* w2    = (const float*)d_in[3];
    const float* b2    = (const float*)d_in[4];
    const float* w3    = (const float*)d_in[5];
    const float* b3    = (const float*)d_in[6];
    const float* cb    = (const float*)d_in[7];
    const float* emb   = (const float*)d_in[8];
    float* out = (float*)d_out;

    float *f1, *f2, *f3, *cbT, *c2p;
    unsigned long long* pkey;
    cudaGetSymbolAddress((void**)&f1,   g_f1);
    cudaGetSymbolAddress((void**)&f2,   g_f2);
    cudaGetSymbolAddress((void**)&f3,   g_f3);
    cudaGetSymbolAddress((void**)&cbT,  g_cbT);
    cudaGetSymbolAddress((void**)&c2p,  g_c2);
    cudaGetSymbolAddress((void**)&pkey, g_pkey);

    // conv1
    conv1_kernel<<<dim3(L1O / 256, C1, NB), 256>>>(audio, w1, b1, f1);
    // codebook prep (independent of conv chain)
    transpose_cb<<<dim3(512 / 32, NCODES / 32), dim3(32, 8)>>>(cb, cbT);
    c2_kernel<<<NCODES / 8, 256>>>(cb, c2p);
    // conv2: 128 -> 256 (relu)
    conv_tiled<C1><<<dim3(L2O / 128, C2C / 128, NB), 256>>>(f1, w2, b2, f2, L1O, L2O, C2C, 1);
    // conv3: 256 -> 512 (no relu)
    conv_tiled<C2C><<<dim3(L3O / 128, C3 / 128, NB), 256>>>(f2, w3, b3, f3, L2O, L3O, C3, 0);
    // VQ GEMM + tile argmin
    vq_gemm<<<dim3(MTOT / VTM, NT), 256>>>(f3, cbT, c2p, pkey);
    // tokens + embedding mean
    finalize_kernel<<<MTOT, 128>>>(pkey, emb, out);
}